// round 14
// baseline (speedup 1.0000x reference)
#include <cuda_runtime.h>
#include <cstdint>

#define PAD 16
#define H 256
#define W 256
#define HO 288
#define WO 288
#define NLAM 96
#define NB 4
#define NK 4
#define NCHUNK 4
#define LCHUNK (NLAM / NCHUNK)   // 24
#define TILE 32
#define REGROWS 56
#define REGCOLS 64               // aligned-float4 fill width
#define RSTRIDE 68               // multiple of 4 -> 16B-aligned row bases
#define NSTAGE 4
#define STAGE_FLOATS (REGROWS * RSTRIDE)
#define SMEM_DYN (NSTAGE * STAGE_FLOATS * 4)   // 60928 B

#define KS 15
#define KR 7

// Partial accumulators: [chunk][b*4+k][HO][WO]  (21.2 MB)
__device__ float g_part[NCHUNK * NB * NK * HO * WO];

typedef unsigned long long ull;

__device__ __forceinline__ ull pack2(float lo, float hi) {
    ull r;
    asm("mov.b64 %0, {%1, %2};" : "=l"(r) : "f"(lo), "f"(hi));
    return r;
}
__device__ __forceinline__ void fma2(ull& d, ull a, ull b) {
    asm("fma.rn.f32x2 %0, %1, %2, %3;" : "=l"(d) : "l"(a), "l"(b), "l"(d));
}
__device__ __forceinline__ void unpack2(ull v, float& lo, float& hi) {
    asm("mov.b64 {%0, %1}, %2;" : "=f"(lo), "=f"(hi) : "l"(v));
}
__device__ __forceinline__ void cp4(uint32_t dst, const float* src, int sz) {
    asm volatile("cp.async.ca.shared.global [%0], [%1], 4, %2;"
                 :: "r"(dst), "l"(src), "r"(sz));
}
__device__ __forceinline__ void cp16(uint32_t dst, const float* src) {
    asm volatile("cp.async.cg.shared.global [%0], [%1], 16;"
                 :: "r"(dst), "l"(src));
}
__device__ __forceinline__ void cp_commit() {
    asm volatile("cp.async.commit_group;");
}

struct __align__(16) WPack { ull w00, w01, w10, w11; };

// ---------------------------------------------------------------------------
// Pass 1: bilinear shift-accumulate over a lambda chunk for all 4 k-sequences.
// 2x2 outputs/thread/k, f32x2 FMA, 4-stage cp.async ring. Fill is bounded by
// the per-lambda used-column count cna. (R13 champion — unchanged.)
// ---------------------------------------------------------------------------
__global__ void __launch_bounds__(256, 3)
shift_acc_kernel(const float* __restrict__ cube,
                 const float* __restrict__ dxv,
                 const float* __restrict__ dyv)
{
    extern __shared__ float s_dyn[];                    // NSTAGE stages
    __shared__ WPack s_wt[LCHUNK * NK];                 // 3 KB
    __shared__ int2  s_off[LCHUNK * NK];                // 768 B
    __shared__ short s_oymin[LCHUNK], s_oxa[LCHUNK], s_rn[LCHUNK], s_cna[LCHUNK];
    __shared__ unsigned char s_okf[LCHUNK], s_fastf[LCHUNK];

    const int tid   = threadIdx.x;
    const int bz    = blockIdx.z;            // b * NCHUNK + chunk
    const int b     = bz >> 2;
    const int chunk = bz & 3;
    const int lam0  = chunk * LCHUNK;
    const int x0    = blockIdx.x * TILE;
    const int y0    = blockIdx.y * TILE;

    // --- Per-(lambda,k) integer offsets + f32x2-packed bilinear weights ---
    for (int i = tid; i < LCHUNK * NK; i += 256) {
        const int l   = i >> 2;
        const int k   = i & 3;
        const int lam = lam0 + l;
        const float sx = -dxv[k * NLAM + lam] - (float)PAD;
        const float sy = -dyv[k * NLAM + lam] - (float)PAD;
        const float fox = floorf(sx), foy = floorf(sy);
        const float fx = sx - fox, fy = sy - foy;
        s_off[i] = make_int2((int)fox, (int)foy);
        const float gxw = 1.f - fx, gyw = 1.f - fy;
        WPack wp;
        wp.w00 = pack2(gyw * gxw, gyw * gxw);
        wp.w01 = pack2(gyw * fx,  gyw * fx);
        wp.w10 = pack2(fy * gxw,  fy * gxw);
        wp.w11 = pack2(fy * fx,   fy * fx);
        s_wt[i] = wp;
    }
    __syncthreads();

    // --- Per-lambda union bounding box over the 4 k offsets (x aligned to 4) ---
    for (int l = tid; l < LCHUNK; l += 256) {
        int oymin = s_off[l * 4].y, oymax = oymin;
        int oxmin = s_off[l * 4].x, oxmax = oxmin;
#pragma unroll
        for (int k = 1; k < NK; ++k) {
            const int oy = s_off[l * 4 + k].y;
            const int ox = s_off[l * 4 + k].x;
            oymin = min(oymin, oy); oymax = max(oymax, oy);
            oxmin = min(oxmin, ox); oxmax = max(oxmax, ox);
        }
        const int oxa = oxmin & ~3;                    // float4-aligned origin
        const int rn  = TILE + 1 + (oymax - oymin);
        const int cna = TILE + 1 + (oxmax - oxa);      // used columns
        s_oymin[l] = (short)oymin;
        s_oxa[l]   = (short)oxa;
        s_rn[l]    = (short)rn;
        s_cna[l]   = (short)cna;
        const bool ok = (rn <= REGROWS && cna <= REGCOLS);
        s_okf[l]   = ok ? 1 : 0;
        const int gy0 = y0 + oymin, gx0 = x0 + oxa;
        s_fastf[l] = (ok && gy0 >= 0 && gy0 + rn <= H &&
                      gx0 >= 0 && gx0 + ((cna + 3) & ~3) <= W) ? 1 : 0;
    }
    __syncthreads();

    const int tx  = tid & 15;    // 2-col group
    const int ty  = tid >> 4;    // 2-row group

    ull acc[NK][2];
#pragma unroll
    for (int k = 0; k < NK; ++k) { acc[k][0] = 0; acc[k][1] = 0; }

    const float* imgb = cube + (size_t)(b * NLAM + lam0) * (H * W);
    const uint32_t sbase0 = (uint32_t)__cvta_generic_to_shared(&s_dyn[0]);
    const ull one2 = pack2(1.f, 1.f);

    auto issue_fill = [&](int lf, int stage) {
        const float* img = imgb + (size_t)lf * (H * W);
        const int rn  = s_rn[lf];
        const int cna = s_cna[lf];
        const int gy0 = y0 + s_oymin[lf];
        const int gx0 = x0 + s_oxa[lf];
        const uint32_t sb = sbase0 + (uint32_t)(stage * STAGE_FLOATS) * 4;
        if (s_fastf[lf]) {
            // interior: 16B cp.async; only quads the compute actually reads.
            const int col4 = (tid & 15) * 4;
            if (col4 < cna) {
                const int r0 = tid >> 4;
                const float* src = img + (size_t)(gy0 + r0) * W + gx0 + col4;
                uint32_t dst = sb + (uint32_t)(r0 * RSTRIDE + col4) * 4;
#pragma unroll
                for (int r = r0; r < REGROWS; r += 16) {
                    if (r < rn) cp16(dst, src);
                    src += 16 * W;
                    dst += 16 * RSTRIDE * 4;
                }
            }
        } else {
            // boundary: scalar cp.async with zero-fill, bounded by cna
            const int c   = tid & 63;
            if (c < cna) {
                const int r0s = tid >> 6;
                const int gx  = gx0 + c;
                const bool xok = (unsigned)gx < (unsigned)W;
                const int gxc = min(max(gx, 0), W - 1);
                uint32_t dst = sb + (uint32_t)(r0s * RSTRIDE + c) * 4;
                for (int r = r0s; r < rn; r += 4) {
                    const int gy = gy0 + r;
                    const bool v = xok && ((unsigned)gy < (unsigned)H);
                    const int gyc = min(max(gy, 0), H - 1);
                    cp4(dst, img + (size_t)gyc * W + gxc, v ? 4 : 0);
                    dst += 4 * RSTRIDE * 4;
                }
            }
        }
    };

    // Prologue: prefetch lambda 0 and 1.
    if (s_okf[0]) issue_fill(0, 0);
    cp_commit();
    if (s_okf[1]) issue_fill(1, 1);
    cp_commit();

    for (int l = 0; l < LCHUNK; ++l) {
        // Issue fill(l+2) BEFORE waiting: it targets stage (l+2)&3 == (l-2)&3,
        // whose compute finished at sync(l-1) for all warps -> race-free.
        if (l + 2 < LCHUNK) {
            if (s_okf[l + 2]) issue_fill(l + 2, (l + 2) & 3);
            cp_commit();
        }
        // Retire fill(l): pending groups are l..min(l+2,LCHUNK-1).
        const int rem = LCHUNK - 1 - l;
        if (rem >= 2)      asm volatile("cp.async.wait_group 2;");
        else if (rem == 1) asm volatile("cp.async.wait_group 1;");
        else               asm volatile("cp.async.wait_group 0;");
        __syncthreads();   // all threads' fill(l) visible; compute(l-1) done

        const float* buf = s_dyn + (l & 3) * STAGE_FLOATS;
        const int oym = s_oymin[l];
        const int oxa = s_oxa[l];

        if (s_okf[l]) {
#pragma unroll
            for (int k = 0; k < NK; ++k) {
                const int2 off = s_off[l * 4 + k];
                const int obase = off.x - oxa + 2 * tx;
                const int rbase = 2 * ty + off.y - oym;
                const float* bp = buf + rbase * RSTRIDE + obase;
                ull p01[3], p12[3];
                if ((obase & 1) == 0) {
#pragma unroll
                    for (int r = 0; r < 3; ++r) {
                        const ull u = *reinterpret_cast<const ull*>(bp + r * RSTRIDE);
                        const float v2s = bp[r * RSTRIDE + 2];
                        float lo_, hi_; unpack2(u, lo_, hi_);
                        p01[r] = u;
                        p12[r] = pack2(hi_, v2s);
                    }
                } else {
#pragma unroll
                    for (int r = 0; r < 3; ++r) {
                        const float v0 = bp[r * RSTRIDE];
                        const ull u = *reinterpret_cast<const ull*>(bp + r * RSTRIDE + 1);
                        float lo_, hi_; unpack2(u, lo_, hi_);
                        p01[r] = pack2(v0, lo_);
                        p12[r] = u;
                    }
                }
                const WPack wp = s_wt[l * 4 + k];
                fma2(acc[k][0], wp.w00, p01[0]);
                fma2(acc[k][0], wp.w01, p12[0]);
                fma2(acc[k][0], wp.w10, p01[1]);
                fma2(acc[k][0], wp.w11, p12[1]);
                fma2(acc[k][1], wp.w00, p01[1]);
                fma2(acc[k][1], wp.w01, p12[1]);
                fma2(acc[k][1], wp.w10, p01[2]);
                fma2(acc[k][1], wp.w11, p12[2]);
            }
        } else {
            // Rare fallback: offsets too spread for the smem tile — global.
            const float* img = imgb + (size_t)l * (H * W);
#pragma unroll
            for (int k = 0; k < NK; ++k) {
                const int2 off = s_off[l * 4 + k];
                float w00, w01, w10, w11, d0;
                unpack2(s_wt[l * 4 + k].w00, w00, d0);
                unpack2(s_wt[l * 4 + k].w01, w01, d0);
                unpack2(s_wt[l * 4 + k].w10, w10, d0);
                unpack2(s_wt[l * 4 + k].w11, w11, d0);
#pragma unroll
                for (int r = 0; r < 2; ++r) {
                    float s[2];
#pragma unroll
                    for (int c = 0; c < 2; ++c) {
                        const int iy0 = y0 + 2 * ty + r + off.y;
                        const int ix0 = x0 + 2 * tx + c + off.x;
                        const bool y0ok = (unsigned)iy0       < (unsigned)H;
                        const bool y1ok = (unsigned)(iy0 + 1) < (unsigned)H;
                        const bool x0ok = (unsigned)ix0       < (unsigned)W;
                        const bool x1ok = (unsigned)(ix0 + 1) < (unsigned)W;
                        const float v00 = (y0ok && x0ok) ? __ldg(&img[iy0 * W + ix0])           : 0.f;
                        const float v01 = (y0ok && x1ok) ? __ldg(&img[iy0 * W + ix0 + 1])       : 0.f;
                        const float v10 = (y1ok && x0ok) ? __ldg(&img[(iy0 + 1) * W + ix0])     : 0.f;
                        const float v11 = (y1ok && x1ok) ? __ldg(&img[(iy0 + 1) * W + ix0 + 1]) : 0.f;
                        s[c] = w00 * v00 + w01 * v01 + w10 * v10 + w11 * v11;
                    }
                    fma2(acc[k][r], one2, pack2(s[0], s[1]));
                }
            }
        }
    }

    // --- Write partials (float2 stores, 2 rows x 2 cols per k) ---
    float* gp = g_part + (size_t)chunk * (NB * NK * HO * WO)
                       + (size_t)b * (NK * HO * WO);
#pragma unroll
    for (int k = 0; k < NK; ++k) {
#pragma unroll
        for (int r = 0; r < 2; ++r) {
            float lo, hi;
            unpack2(acc[k][r], lo, hi);
            *reinterpret_cast<float2*>(
                &gp[(size_t)k * (HO * WO) + (y0 + 2 * ty + r) * WO + x0 + 2 * tx]) =
                make_float2(lo, hi);
        }
    }
}

// ---------------------------------------------------------------------------
// Pass 2: 15x15 PSF conv, 64x48 tile, 4x3 outputs/thread, f32x2 FMA.
// 17 row-loads serve 12 outputs -> 37% fewer LDS per output than 4x2.
// ---------------------------------------------------------------------------
#define P2TX 64
#define P2TY 48
#define P2RC 78      // region cols: 64 + 14
#define P2RR 62      // region rows: 48 + 14
#define P2S  80      // smem stride (float4-aligned)

__global__ void __launch_bounds__(256, 3)
psf_conv_kernel(const float* __restrict__ psf, float* __restrict__ out)
{
    __shared__ float s_acc[P2RR * P2S];        // 19.8 KB
    __shared__ ull   s_psf2[KS * KS];          // 1.8 KB

    const int tid = threadIdx.x;
    const int p   = blockIdx.z;                // plane: b*4+k
    const int x0  = blockIdx.x * P2TX;
    const int y0  = blockIdx.y * P2TY;

    if (tid < KS * KS) {
        const float w = __ldg(&psf[tid]);
        s_psf2[tid] = pack2(w, w);
    }

    const float* p0 = g_part + (size_t)p * (HO * WO);
    const size_t  pstep = (size_t)(NB * NK) * (HO * WO);

    // Load region: cols 0..63
    {
        const int c  = tid & 63;
        const int gx = x0 + c - KR;
        const bool xok = (unsigned)gx < (unsigned)WO;
#pragma unroll 4
        for (int r = tid >> 6; r < P2RR; r += 4) {
            const int gy = y0 + r - KR;
            float v = 0.f;
            if (xok && (unsigned)gy < (unsigned)HO) {
                const int idx = gy * WO + gx;
                v = __ldg(&p0[idx]) + __ldg(&p0[idx + pstep])
                  + __ldg(&p0[idx + 2 * pstep]) + __ldg(&p0[idx + 3 * pstep]);
            }
            s_acc[r * P2S + c] = v;
        }
    }
    // Load region: cols 64..77
    {
        const int c  = 64 + (tid & 15);
        const int gx = x0 + c - KR;
        const bool cok = c < P2RC;
        const bool xok = cok && (unsigned)gx < (unsigned)WO;
#pragma unroll
        for (int r = tid >> 4; r < P2RR; r += 16) {
            const int gy = y0 + r - KR;
            float v = 0.f;
            if (xok && (unsigned)gy < (unsigned)HO) {
                const int idx = gy * WO + gx;
                v = __ldg(&p0[idx]) + __ldg(&p0[idx + pstep])
                  + __ldg(&p0[idx + 2 * pstep]) + __ldg(&p0[idx + 3 * pstep]);
            }
            if (cok) s_acc[r * P2S + c] = v;
        }
    }
    __syncthreads();

    const int tx = (tid & 15) * 4;   // 0..60
    const int ty = (tid >> 4) * 3;   // 0..45

    ull A0[2] = {0, 0}, A1[2] = {0, 0}, A2[2] = {0, 0};
    ull pp[17];

    auto load_pack = [&](int v) {
        float row[20];
        const float4* rp = reinterpret_cast<const float4*>(&s_acc[(ty + v) * P2S + tx]);
#pragma unroll
        for (int q = 0; q < 5; ++q) {
            const float4 t = rp[q];
            row[4*q+0] = t.x; row[4*q+1] = t.y; row[4*q+2] = t.z; row[4*q+3] = t.w;
        }
#pragma unroll
        for (int j = 0; j < 17; ++j) pp[j] = pack2(row[j], row[j+1]);
    };

    auto dorow = [&](ull* Ar, int ky) {
        const ull* wrow = &s_psf2[ky * KS];
#pragma unroll
        for (int kx = 0; kx < KS; ++kx) {
            const ull w = wrow[kx];
            fma2(Ar[0], w, pp[kx]);
            fma2(Ar[1], w, pp[kx + 2]);
        }
    };

    // v = 0: row0 only
    load_pack(0);
    dorow(A0, 0);
    // v = 1: row0 + row1
    load_pack(1);
    dorow(A0, 1);
    dorow(A1, 0);
    // v = 2..14: all three rows
#pragma unroll 2
    for (int v = 2; v < KS; ++v) {
        load_pack(v);
        dorow(A0, v);
        dorow(A1, v - 1);
        dorow(A2, v - 2);
    }
    // v = 15: rows 1,2
    load_pack(15);
    dorow(A1, 14);
    dorow(A2, 13);
    // v = 16: row 2
    load_pack(16);
    dorow(A2, 14);

    float* op = out + (size_t)p * (HO * WO);
    const int ybase = y0 + ty;
    const int xbase = x0 + tx;
    float lo, hi;
    if (xbase < WO) {
        unpack2(A0[0], lo, hi);
        *reinterpret_cast<float2*>(&op[ybase * WO + xbase]) = make_float2(lo, hi);
        unpack2(A1[0], lo, hi);
        *reinterpret_cast<float2*>(&op[(ybase + 1) * WO + xbase]) = make_float2(lo, hi);
        unpack2(A2[0], lo, hi);
        *reinterpret_cast<float2*>(&op[(ybase + 2) * WO + xbase]) = make_float2(lo, hi);
    }
    if (xbase + 2 < WO) {
        unpack2(A0[1], lo, hi);
        *reinterpret_cast<float2*>(&op[ybase * WO + xbase + 2]) = make_float2(lo, hi);
        unpack2(A1[1], lo, hi);
        *reinterpret_cast<float2*>(&op[(ybase + 1) * WO + xbase + 2]) = make_float2(lo, hi);
        unpack2(A2[1], lo, hi);
        *reinterpret_cast<float2*>(&op[(ybase + 2) * WO + xbase + 2]) = make_float2(lo, hi);
    }
}

// ---------------------------------------------------------------------------
extern "C" void kernel_launch(void* const* d_in, const int* in_sizes, int n_in,
                              void* d_out, int out_size)
{
    const float* cube = (const float*)d_in[0];   // (4, 96, 256, 256)
    const float* dx   = (const float*)d_in[1];   // (4, 96)
    const float* dy   = (const float*)d_in[2];   // (4, 96)
    const float* psf  = (const float*)d_in[3];   // (15, 15)
    float* out        = (float*)d_out;           // (4, 4, 288, 288)

    cudaFuncSetAttribute(shift_acc_kernel,
                         cudaFuncAttributeMaxDynamicSharedMemorySize, SMEM_DYN);

    dim3 g1(WO / TILE, HO / TILE, NB * NCHUNK);           // 9 x 9 x 16
    shift_acc_kernel<<<g1, 256, SMEM_DYN>>>(cube, dx, dy);

    dim3 g2((WO + P2TX - 1) / P2TX, HO / P2TY, NB * NK);  // 5 x 6 x 16
    psf_conv_kernel<<<g2, 256>>>(psf, out);
}

// round 16
// speedup vs baseline: 1.3165x; 1.3165x over previous
#include <cuda_runtime.h>
#include <cuda.h>
#include <cstdint>

#define PAD 16
#define H 256
#define W 256
#define HO 288
#define WO 288
#define NLAM 96
#define NB 4
#define NK 4
#define NCHUNK 4
#define LCHUNK (NLAM / NCHUNK)   // 24
#define TILE 32
#define REGROWS 56
#define REGCOLS 56
#define RSTRIDE 56               // TMA-compact rows (224B, 16B-multiple)
#define NSTAGE 4
#define STAGE_FLOATS (REGROWS * RSTRIDE)       // 3136
#define SMEM_DYN (NSTAGE * STAGE_FLOATS * 4 + 128)   // +128 for 128B realign
#define TMA_BYTES (STAGE_FLOATS * 4)           // 12544 B per box

#define KS 15
#define KR 7

// Partial accumulators: [chunk][b*4+k][HO][WO]  (21.2 MB)
__device__ float g_part[NCHUNK * NB * NK * HO * WO];

typedef unsigned long long ull;

__device__ __forceinline__ ull pack2(float lo, float hi) {
    ull r;
    asm("mov.b64 %0, {%1, %2};" : "=l"(r) : "f"(lo), "f"(hi));
    return r;
}
__device__ __forceinline__ void fma2(ull& d, ull a, ull b) {
    asm("fma.rn.f32x2 %0, %1, %2, %3;" : "=l"(d) : "l"(a), "l"(b), "l"(d));
}
__device__ __forceinline__ void unpack2(ull v, float& lo, float& hi) {
    asm("mov.b64 {%0, %1}, %2;" : "=f"(lo), "=f"(hi) : "l"(v));
}

__device__ __forceinline__ void mbar_init(uint32_t mbar, uint32_t cnt) {
    asm volatile("mbarrier.init.shared.b64 [%0], %1;" :: "r"(mbar), "r"(cnt) : "memory");
}
__device__ __forceinline__ void mbar_expect_tx(uint32_t mbar, uint32_t bytes) {
    asm volatile("mbarrier.arrive.expect_tx.shared.b64 _, [%0], %1;"
                 :: "r"(mbar), "r"(bytes) : "memory");
}
__device__ __forceinline__ void mbar_arrive(uint32_t mbar) {
    asm volatile("mbarrier.arrive.shared.b64 _, [%0];" :: "r"(mbar) : "memory");
}
__device__ __forceinline__ void mbar_wait(uint32_t mbar, uint32_t parity) {
    asm volatile(
        "{\n\t"
        ".reg .pred P;\n\t"
        "WAIT_%=:\n\t"
        "mbarrier.try_wait.parity.acquire.cta.shared::cta.b64 P, [%0], %1;\n\t"
        "@!P bra WAIT_%=;\n\t"
        "}"
        :: "r"(mbar), "r"(parity) : "memory");
}
__device__ __forceinline__ void tma_load3d(uint32_t dst, const CUtensorMap* map,
                                           int cx, int cy, int cz, uint32_t mbar) {
    asm volatile(
        "cp.async.bulk.tensor.3d.shared::cta.global.tile.mbarrier::complete_tx::bytes "
        "[%0], [%1, {%2, %3, %4}], [%5];"
        :: "r"(dst), "l"(map), "r"(cx), "r"(cy), "r"(cz), "r"(mbar) : "memory");
}

struct __align__(16) WPack { ull w00, w01, w10, w11; };

// ---------------------------------------------------------------------------
// Pass 1: bilinear shift-accumulate over a lambda chunk for all 4 k-sequences.
// 2x2 outputs/thread/k, f32x2 FMA. Fill = ONE 3D TMA per lambda (56x56 box,
// zero-fill OOB), 4-stage ring with mbarrier completion. The dynamic-smem
// base is realigned to 128B in-kernel (TMA dst requirement).
// ---------------------------------------------------------------------------
__global__ void __launch_bounds__(256, 3)
shift_acc_kernel(const __grid_constant__ CUtensorMap tmap,
                 const float* __restrict__ cube,
                 const float* __restrict__ dxv,
                 const float* __restrict__ dyv)
{
    extern __shared__ float s_raw[];
    __shared__ WPack s_wt[LCHUNK * NK];                 // 3 KB
    __shared__ int2  s_off[LCHUNK * NK];                // 768 B
    __shared__ short s_oymin[LCHUNK], s_oxa[LCHUNK];
    __shared__ unsigned char s_okf[LCHUNK];
    __shared__ __align__(8) ull s_mbar[NSTAGE];

    // 128B-align the stage buffer base (cp.async.bulk.tensor dst requirement)
    const uint32_t raw32  = (uint32_t)__cvta_generic_to_shared(&s_raw[0]);
    const uint32_t sbase0 = (raw32 + 127u) & ~127u;
    float* s_dyn = s_raw + (sbase0 - raw32) / 4;

    const int tid   = threadIdx.x;
    const int bz    = blockIdx.z;            // b * NCHUNK + chunk
    const int b     = bz >> 2;
    const int chunk = bz & 3;
    const int lam0  = chunk * LCHUNK;
    const int x0    = blockIdx.x * TILE;
    const int y0    = blockIdx.y * TILE;
    const int pbase = b * NLAM + lam0;       // z-plane base in the cube tensor

    const uint32_t mb0 = (uint32_t)__cvta_generic_to_shared(&s_mbar[0]);

    if (tid == 0) {
#pragma unroll
        for (int s = 0; s < NSTAGE; ++s) mbar_init(mb0 + 8 * s, 1);
    }

    // --- Per-(lambda,k) integer offsets + f32x2-packed bilinear weights ---
    for (int i = tid; i < LCHUNK * NK; i += 256) {
        const int l   = i >> 2;
        const int k   = i & 3;
        const int lam = lam0 + l;
        const float sx = -dxv[k * NLAM + lam] - (float)PAD;
        const float sy = -dyv[k * NLAM + lam] - (float)PAD;
        const float fox = floorf(sx), foy = floorf(sy);
        const float fx = sx - fox, fy = sy - foy;
        s_off[i] = make_int2((int)fox, (int)foy);
        const float gxw = 1.f - fx, gyw = 1.f - fy;
        WPack wp;
        wp.w00 = pack2(gyw * gxw, gyw * gxw);
        wp.w01 = pack2(gyw * fx,  gyw * fx);
        wp.w10 = pack2(fy * gxw,  fy * gxw);
        wp.w11 = pack2(fy * fx,   fy * fx);
        s_wt[i] = wp;
    }
    __syncthreads();

    // --- Per-lambda union bounding box over the 4 k offsets (x aligned to 4) ---
    for (int l = tid; l < LCHUNK; l += 256) {
        int oymin = s_off[l * 4].y, oymax = oymin;
        int oxmin = s_off[l * 4].x, oxmax = oxmin;
#pragma unroll
        for (int k = 1; k < NK; ++k) {
            const int oy = s_off[l * 4 + k].y;
            const int ox = s_off[l * 4 + k].x;
            oymin = min(oymin, oy); oymax = max(oymax, oy);
            oxmin = min(oxmin, ox); oxmax = max(oxmax, ox);
        }
        const int oxa = oxmin & ~3;                    // float4-aligned origin
        const int rn  = TILE + 1 + (oymax - oymin);
        const int cna = TILE + 1 + (oxmax - oxa);      // used columns
        s_oymin[l] = (short)oymin;
        s_oxa[l]   = (short)oxa;
        s_okf[l]   = (rn <= REGROWS && cna <= REGCOLS) ? 1 : 0;
    }
    __syncthreads();   // mbarrier init + metadata visible

    const int tx  = tid & 15;    // 2-col group
    const int ty  = tid >> 4;    // 2-row group

    ull acc[NK][2];
#pragma unroll
    for (int k = 0; k < NK; ++k) { acc[k][0] = 0; acc[k][1] = 0; }

    const float* imgb = cube + (size_t)pbase * (H * W);
    const ull one2 = pack2(1.f, 1.f);

    // One-thread TMA issue for lambda lf into stage (expect_tx + bulk load).
    auto issue = [&](int lf, int stage) {
        const uint32_t mbar = mb0 + 8 * stage;
        if (s_okf[lf]) {
            mbar_expect_tx(mbar, TMA_BYTES);
            tma_load3d(sbase0 + (uint32_t)(stage * STAGE_FLOATS) * 4, &tmap,
                       x0 + (int)s_oxa[lf], y0 + (int)s_oymin[lf], pbase + lf,
                       mbar);
        } else {
            mbar_arrive(mbar);   // flip phase; compute takes global fallback
        }
    };

    // Prologue: issue lambda 0 and 1 (stages 0, 1 — fresh).
    if (tid == 0) { issue(0, 0); issue(1, 1); }

    for (int l = 0; l < LCHUNK; ++l) {
        __syncthreads();   // all threads finished compute(l-1) (=> l-2 free)
        // Issue fill(l+2): targets stage (l+2)&3 == (l-2)&3 — free per above.
        if (tid == 0 && l + 2 < LCHUNK) issue(l + 2, (l + 2) & 3);
        // Wait for fill(l): stage l&3, phase (l>>2)&1.
        mbar_wait(mb0 + 8 * (l & 3), (l >> 2) & 1);

        const float* buf = s_dyn + (l & 3) * STAGE_FLOATS;
        const int oym = s_oymin[l];
        const int oxa = s_oxa[l];

        if (s_okf[l]) {
#pragma unroll
            for (int k = 0; k < NK; ++k) {
                const int2 off = s_off[l * 4 + k];
                const int obase = off.x - oxa + 2 * tx;
                const int rbase = 2 * ty + off.y - oym;
                const float* bp = buf + rbase * RSTRIDE + obase;
                ull p01[3], p12[3];
                if ((obase & 1) == 0) {
#pragma unroll
                    for (int r = 0; r < 3; ++r) {
                        const ull u = *reinterpret_cast<const ull*>(bp + r * RSTRIDE);
                        const float v2s = bp[r * RSTRIDE + 2];
                        float lo_, hi_; unpack2(u, lo_, hi_);
                        p01[r] = u;
                        p12[r] = pack2(hi_, v2s);
                    }
                } else {
#pragma unroll
                    for (int r = 0; r < 3; ++r) {
                        const float v0 = bp[r * RSTRIDE];
                        const ull u = *reinterpret_cast<const ull*>(bp + r * RSTRIDE + 1);
                        float lo_, hi_; unpack2(u, lo_, hi_);
                        p01[r] = pack2(v0, lo_);
                        p12[r] = u;
                    }
                }
                const WPack wp = s_wt[l * 4 + k];
                fma2(acc[k][0], wp.w00, p01[0]);
                fma2(acc[k][0], wp.w01, p12[0]);
                fma2(acc[k][0], wp.w10, p01[1]);
                fma2(acc[k][0], wp.w11, p12[1]);
                fma2(acc[k][1], wp.w00, p01[1]);
                fma2(acc[k][1], wp.w01, p12[1]);
                fma2(acc[k][1], wp.w10, p01[2]);
                fma2(acc[k][1], wp.w11, p12[2]);
            }
        } else {
            // Rare fallback: offsets too spread for the smem tile — global.
            const float* img = imgb + (size_t)l * (H * W);
#pragma unroll
            for (int k = 0; k < NK; ++k) {
                const int2 off = s_off[l * 4 + k];
                float w00, w01, w10, w11, d0;
                unpack2(s_wt[l * 4 + k].w00, w00, d0);
                unpack2(s_wt[l * 4 + k].w01, w01, d0);
                unpack2(s_wt[l * 4 + k].w10, w10, d0);
                unpack2(s_wt[l * 4 + k].w11, w11, d0);
#pragma unroll
                for (int r = 0; r < 2; ++r) {
                    float s[2];
#pragma unroll
                    for (int c = 0; c < 2; ++c) {
                        const int iy0 = y0 + 2 * ty + r + off.y;
                        const int ix0 = x0 + 2 * tx + c + off.x;
                        const bool y0ok = (unsigned)iy0       < (unsigned)H;
                        const bool y1ok = (unsigned)(iy0 + 1) < (unsigned)H;
                        const bool x0ok = (unsigned)ix0       < (unsigned)W;
                        const bool x1ok = (unsigned)(ix0 + 1) < (unsigned)W;
                        const float v00 = (y0ok && x0ok) ? __ldg(&img[iy0 * W + ix0])           : 0.f;
                        const float v01 = (y0ok && x1ok) ? __ldg(&img[iy0 * W + ix0 + 1])       : 0.f;
                        const float v10 = (y1ok && x0ok) ? __ldg(&img[(iy0 + 1) * W + ix0])     : 0.f;
                        const float v11 = (y1ok && x1ok) ? __ldg(&img[(iy0 + 1) * W + ix0 + 1]) : 0.f;
                        s[c] = w00 * v00 + w01 * v01 + w10 * v10 + w11 * v11;
                    }
                    fma2(acc[k][r], one2, pack2(s[0], s[1]));
                }
            }
        }
    }

    // --- Write partials (float2 stores, 2 rows x 2 cols per k) ---
    float* gp = g_part + (size_t)chunk * (NB * NK * HO * WO)
                       + (size_t)b * (NK * HO * WO);
#pragma unroll
    for (int k = 0; k < NK; ++k) {
#pragma unroll
        for (int r = 0; r < 2; ++r) {
            float lo, hi;
            unpack2(acc[k][r], lo, hi);
            *reinterpret_cast<float2*>(
                &gp[(size_t)k * (HO * WO) + (y0 + 2 * ty + r) * WO + x0 + 2 * tx]) =
                make_float2(lo, hi);
        }
    }
}

// ---------------------------------------------------------------------------
// Pass 2: 15x15 PSF conv, 64x32 tile, 4x2 outputs/thread, f32x2 FMA.
// (R13 champion — unchanged.)
// ---------------------------------------------------------------------------
#define P2TX 64
#define P2TY 32
#define P2RC 78      // region cols: 64 + 14
#define P2RR 46      // region rows: 32 + 14
#define P2S  80      // smem stride (float4-aligned)

__global__ void __launch_bounds__(256)
psf_conv_kernel(const float* __restrict__ psf, float* __restrict__ out)
{
    __shared__ float s_acc[P2RR * P2S];        // 14.7 KB
    __shared__ ull   s_psf2[KS * KS];          // 1.8 KB

    const int tid = threadIdx.x;
    const int p   = blockIdx.z;                // plane: b*4+k
    const int x0  = blockIdx.x * P2TX;
    const int y0  = blockIdx.y * P2TY;

    if (tid < KS * KS) {
        const float w = __ldg(&psf[tid]);
        s_psf2[tid] = pack2(w, w);
    }

    const float* p0 = g_part + (size_t)p * (HO * WO);
    const size_t  pstep = (size_t)(NB * NK) * (HO * WO);

    // Load region: cols 0..63
    {
        const int c  = tid & 63;
        const int gx = x0 + c - KR;
        const bool xok = (unsigned)gx < (unsigned)WO;
#pragma unroll 4
        for (int r = tid >> 6; r < P2RR; r += 4) {
            const int gy = y0 + r - KR;
            float v = 0.f;
            if (xok && (unsigned)gy < (unsigned)HO) {
                const int idx = gy * WO + gx;
                v = __ldg(&p0[idx]) + __ldg(&p0[idx + pstep])
                  + __ldg(&p0[idx + 2 * pstep]) + __ldg(&p0[idx + 3 * pstep]);
            }
            s_acc[r * P2S + c] = v;
        }
    }
    // Load region: cols 64..77
    {
        const int c  = 64 + (tid & 15);
        const int gx = x0 + c - KR;
        const bool cok = c < P2RC;
        const bool xok = cok && (unsigned)gx < (unsigned)WO;
#pragma unroll
        for (int r = tid >> 4; r < P2RR; r += 16) {
            const int gy = y0 + r - KR;
            float v = 0.f;
            if (xok && (unsigned)gy < (unsigned)HO) {
                const int idx = gy * WO + gx;
                v = __ldg(&p0[idx]) + __ldg(&p0[idx + pstep])
                  + __ldg(&p0[idx + 2 * pstep]) + __ldg(&p0[idx + 3 * pstep]);
            }
            if (cok) s_acc[r * P2S + c] = v;
        }
    }
    __syncthreads();

    const int tx = (tid & 15) * 4;   // 0..60
    const int ty = (tid >> 4) * 2;   // 0..30

    ull acc00 = 0, acc01 = 0, acc10 = 0, acc11 = 0;
    ull pp[17];

    auto load_pack = [&](int v) {
        float row[20];
        const float4* rp = reinterpret_cast<const float4*>(&s_acc[(ty + v) * P2S + tx]);
#pragma unroll
        for (int q = 0; q < 5; ++q) {
            const float4 t = rp[q];
            row[4*q+0] = t.x; row[4*q+1] = t.y; row[4*q+2] = t.z; row[4*q+3] = t.w;
        }
#pragma unroll
        for (int j = 0; j < 17; ++j) pp[j] = pack2(row[j], row[j+1]);
    };

    // v = 0: contributes only to output row 0 (ky = 0)
    load_pack(0);
#pragma unroll
    for (int kx = 0; kx < KS; ++kx) {
        const ull w = s_psf2[kx];
        fma2(acc00, w, pp[kx]);
        fma2(acc01, w, pp[kx + 2]);
    }
    // v = 1..14: contributes to both output rows
#pragma unroll 2
    for (int v = 1; v < KS; ++v) {
        load_pack(v);
#pragma unroll
        for (int kx = 0; kx < KS; ++kx) {
            const ull w0 = s_psf2[v * KS + kx];         // row 0, ky = v
            fma2(acc00, w0, pp[kx]);
            fma2(acc01, w0, pp[kx + 2]);
            const ull w1 = s_psf2[(v - 1) * KS + kx];   // row 1, ky = v-1
            fma2(acc10, w1, pp[kx]);
            fma2(acc11, w1, pp[kx + 2]);
        }
    }
    // v = 15: contributes only to output row 1 (ky = 14)
    load_pack(KS);
#pragma unroll
    for (int kx = 0; kx < KS; ++kx) {
        const ull w = s_psf2[(KS - 1) * KS + kx];
        fma2(acc10, w, pp[kx]);
        fma2(acc11, w, pp[kx + 2]);
    }

    float* op = out + (size_t)p * (HO * WO);
    const int ybase = y0 + ty;
    const int xbase = x0 + tx;
    float lo, hi;
    if (xbase < WO) {
        unpack2(acc00, lo, hi);
        *reinterpret_cast<float2*>(&op[ybase * WO + xbase]) = make_float2(lo, hi);
        unpack2(acc10, lo, hi);
        *reinterpret_cast<float2*>(&op[(ybase + 1) * WO + xbase]) = make_float2(lo, hi);
    }
    if (xbase + 2 < WO) {
        unpack2(acc01, lo, hi);
        *reinterpret_cast<float2*>(&op[ybase * WO + xbase + 2]) = make_float2(lo, hi);
        unpack2(acc11, lo, hi);
        *reinterpret_cast<float2*>(&op[(ybase + 1) * WO + xbase + 2]) = make_float2(lo, hi);
    }
}

// ---------------------------------------------------------------------------
// Host: build the cube tensor map (driver entry point via cudart — no -lcuda).
// ---------------------------------------------------------------------------
typedef CUresult (*PFN_tmapEncode)(
    CUtensorMap*, CUtensorMapDataType, cuuint32_t, void*,
    const cuuint64_t*, const cuuint64_t*, const cuuint32_t*, const cuuint32_t*,
    CUtensorMapInterleave, CUtensorMapSwizzle, CUtensorMapL2promotion,
    CUtensorMapFloatOOBfill);

extern "C" void kernel_launch(void* const* d_in, const int* in_sizes, int n_in,
                              void* d_out, int out_size)
{
    const float* cube = (const float*)d_in[0];   // (4, 96, 256, 256)
    const float* dx   = (const float*)d_in[1];   // (4, 96)
    const float* dy   = (const float*)d_in[2];   // (4, 96)
    const float* psf  = (const float*)d_in[3];   // (15, 15)
    float* out        = (float*)d_out;           // (4, 4, 288, 288)

    // Fetch cuTensorMapEncodeTiled through cudart (works without -lcuda).
    void* fp = nullptr;
#if CUDART_VERSION >= 12050
    cudaDriverEntryPointQueryResult qres;
    cudaGetDriverEntryPointByVersion("cuTensorMapEncodeTiled", &fp, 12000,
                                     cudaEnableDefault, &qres);
#else
    cudaGetDriverEntryPoint("cuTensorMapEncodeTiled", &fp, cudaEnableDefault);
#endif
    PFN_tmapEncode encode = (PFN_tmapEncode)fp;

    CUtensorMap tmap{};
    {
        cuuint64_t dims[3]    = {(cuuint64_t)W, (cuuint64_t)H,
                                 (cuuint64_t)(NB * NLAM)};
        cuuint64_t strides[2] = {(cuuint64_t)W * 4,
                                 (cuuint64_t)W * H * 4};
        cuuint32_t box[3]     = {REGCOLS, REGROWS, 1};
        cuuint32_t estr[3]    = {1, 1, 1};
        encode(&tmap, CU_TENSOR_MAP_DATA_TYPE_FLOAT32, 3, (void*)cube,
               dims, strides, box, estr,
               CU_TENSOR_MAP_INTERLEAVE_NONE, CU_TENSOR_MAP_SWIZZLE_NONE,
               CU_TENSOR_MAP_L2_PROMOTION_L2_128B,
               CU_TENSOR_MAP_FLOAT_OOB_FILL_NONE);
    }

    cudaFuncSetAttribute(shift_acc_kernel,
                         cudaFuncAttributeMaxDynamicSharedMemorySize, SMEM_DYN);

    dim3 g1(WO / TILE, HO / TILE, NB * NCHUNK);           // 9 x 9 x 16
    shift_acc_kernel<<<g1, 256, SMEM_DYN>>>(tmap, cube, dx, dy);

    dim3 g2((WO + P2TX - 1) / P2TX, HO / P2TY, NB * NK);  // 5 x 9 x 16
    psf_conv_kernel<<<g2, 256>>>(psf, out);
}

// round 17
// speedup vs baseline: 1.3273x; 1.0082x over previous
#include <cuda_runtime.h>
#include <cuda.h>
#include <cstdint>

#define PAD 16
#define H 256
#define W 256
#define HO 288
#define WO 288
#define NLAM 96
#define NB 4
#define NK 4
#define NCHUNK 4
#define LCHUNK (NLAM / NCHUNK)   // 24
#define TILE 32
#define REGROWS 56
#define REGCOLS 56
#define RSTRIDE 56               // TMA-compact rows (224B, 16B-multiple)
#define NSTAGE 5
#define PFD 3                    // prefetch distance (lambdas ahead)
#define STAGE_FLOATS (REGROWS * RSTRIDE)       // 3136
#define SMEM_DYN (NSTAGE * STAGE_FLOATS * 4 + 128)   // +128 for 128B realign
#define TMA_BYTES (STAGE_FLOATS * 4)           // 12544 B per box

#define KS 15
#define KR 7

// Partial accumulators: [chunk][b*4+k][HO][WO]  (21.2 MB)
__device__ float g_part[NCHUNK * NB * NK * HO * WO];

typedef unsigned long long ull;

__device__ __forceinline__ ull pack2(float lo, float hi) {
    ull r;
    asm("mov.b64 %0, {%1, %2};" : "=l"(r) : "f"(lo), "f"(hi));
    return r;
}
__device__ __forceinline__ void fma2(ull& d, ull a, ull b) {
    asm("fma.rn.f32x2 %0, %1, %2, %3;" : "=l"(d) : "l"(a), "l"(b), "l"(d));
}
__device__ __forceinline__ void unpack2(ull v, float& lo, float& hi) {
    asm("mov.b64 {%0, %1}, %2;" : "=f"(lo), "=f"(hi) : "l"(v));
}

__device__ __forceinline__ void mbar_init(uint32_t mbar, uint32_t cnt) {
    asm volatile("mbarrier.init.shared.b64 [%0], %1;" :: "r"(mbar), "r"(cnt) : "memory");
}
__device__ __forceinline__ void mbar_expect_tx(uint32_t mbar, uint32_t bytes) {
    asm volatile("mbarrier.arrive.expect_tx.shared.b64 _, [%0], %1;"
                 :: "r"(mbar), "r"(bytes) : "memory");
}
__device__ __forceinline__ void mbar_arrive(uint32_t mbar) {
    asm volatile("mbarrier.arrive.shared.b64 _, [%0];" :: "r"(mbar) : "memory");
}
__device__ __forceinline__ void mbar_wait(uint32_t mbar, uint32_t parity) {
    asm volatile(
        "{\n\t"
        ".reg .pred P;\n\t"
        "WAIT_%=:\n\t"
        "mbarrier.try_wait.parity.acquire.cta.shared::cta.b64 P, [%0], %1;\n\t"
        "@!P bra WAIT_%=;\n\t"
        "}"
        :: "r"(mbar), "r"(parity) : "memory");
}
__device__ __forceinline__ void tma_load3d(uint32_t dst, const CUtensorMap* map,
                                           int cx, int cy, int cz, uint32_t mbar) {
    asm volatile(
        "cp.async.bulk.tensor.3d.shared::cta.global.tile.mbarrier::complete_tx::bytes "
        "[%0], [%1, {%2, %3, %4}], [%5];"
        :: "r"(dst), "l"(map), "r"(cx), "r"(cy), "r"(cz), "r"(mbar) : "memory");
}

struct __align__(16) WPack { ull w00, w01, w10, w11; };

// ---------------------------------------------------------------------------
// Pass 1: bilinear shift-accumulate over a lambda chunk for all 4 k-sequences.
// 2x2 outputs/thread/k, f32x2 FMA. Fill = ONE 3D TMA per lambda (56x56 box,
// zero-fill OOB), 5-stage ring, prefetch distance 3, mbarrier completion.
// ---------------------------------------------------------------------------
__global__ void __launch_bounds__(256, 3)
shift_acc_kernel(const __grid_constant__ CUtensorMap tmap,
                 const float* __restrict__ cube,
                 const float* __restrict__ dxv,
                 const float* __restrict__ dyv)
{
    extern __shared__ float s_raw[];
    __shared__ WPack s_wt[LCHUNK * NK];                 // 3 KB
    __shared__ int2  s_off[LCHUNK * NK];                // 768 B
    __shared__ short s_oymin[LCHUNK], s_oxa[LCHUNK];
    __shared__ unsigned char s_okf[LCHUNK];
    __shared__ __align__(8) ull s_mbar[NSTAGE];

    // 128B-align the stage buffer base (cp.async.bulk.tensor dst requirement)
    const uint32_t raw32  = (uint32_t)__cvta_generic_to_shared(&s_raw[0]);
    const uint32_t sbase0 = (raw32 + 127u) & ~127u;
    float* s_dyn = s_raw + (sbase0 - raw32) / 4;

    const int tid   = threadIdx.x;
    const int bz    = blockIdx.z;            // b * NCHUNK + chunk
    const int b     = bz >> 2;
    const int chunk = bz & 3;
    const int lam0  = chunk * LCHUNK;
    const int x0    = blockIdx.x * TILE;
    const int y0    = blockIdx.y * TILE;
    const int pbase = b * NLAM + lam0;       // z-plane base in the cube tensor

    const uint32_t mb0 = (uint32_t)__cvta_generic_to_shared(&s_mbar[0]);

    if (tid == 0) {
#pragma unroll
        for (int s = 0; s < NSTAGE; ++s) mbar_init(mb0 + 8 * s, 1);
    }

    // --- Per-(lambda,k) integer offsets + f32x2-packed bilinear weights ---
    for (int i = tid; i < LCHUNK * NK; i += 256) {
        const int l   = i >> 2;
        const int k   = i & 3;
        const int lam = lam0 + l;
        const float sx = -dxv[k * NLAM + lam] - (float)PAD;
        const float sy = -dyv[k * NLAM + lam] - (float)PAD;
        const float fox = floorf(sx), foy = floorf(sy);
        const float fx = sx - fox, fy = sy - foy;
        s_off[i] = make_int2((int)fox, (int)foy);
        const float gxw = 1.f - fx, gyw = 1.f - fy;
        WPack wp;
        wp.w00 = pack2(gyw * gxw, gyw * gxw);
        wp.w01 = pack2(gyw * fx,  gyw * fx);
        wp.w10 = pack2(fy * gxw,  fy * gxw);
        wp.w11 = pack2(fy * fx,   fy * fx);
        s_wt[i] = wp;
    }
    __syncthreads();

    // --- Per-lambda union bounding box over the 4 k offsets (x aligned to 4) ---
    for (int l = tid; l < LCHUNK; l += 256) {
        int oymin = s_off[l * 4].y, oymax = oymin;
        int oxmin = s_off[l * 4].x, oxmax = oxmin;
#pragma unroll
        for (int k = 1; k < NK; ++k) {
            const int oy = s_off[l * 4 + k].y;
            const int ox = s_off[l * 4 + k].x;
            oymin = min(oymin, oy); oymax = max(oymax, oy);
            oxmin = min(oxmin, ox); oxmax = max(oxmax, ox);
        }
        const int oxa = oxmin & ~3;                    // float4-aligned origin
        const int rn  = TILE + 1 + (oymax - oymin);
        const int cna = TILE + 1 + (oxmax - oxa);      // used columns
        s_oymin[l] = (short)oymin;
        s_oxa[l]   = (short)oxa;
        s_okf[l]   = (rn <= REGROWS && cna <= REGCOLS) ? 1 : 0;
    }
    __syncthreads();   // mbarrier init + metadata visible

    const int tx  = tid & 15;    // 2-col group
    const int ty  = tid >> 4;    // 2-row group

    ull acc[NK][2];
#pragma unroll
    for (int k = 0; k < NK; ++k) { acc[k][0] = 0; acc[k][1] = 0; }

    const float* imgb = cube + (size_t)pbase * (H * W);
    const ull one2 = pack2(1.f, 1.f);

    // One-thread TMA issue for lambda lf into stage (expect_tx + bulk load).
    auto issue = [&](int lf, int stage) {
        const uint32_t mbar = mb0 + 8 * stage;
        if (s_okf[lf]) {
            mbar_expect_tx(mbar, TMA_BYTES);
            tma_load3d(sbase0 + (uint32_t)(stage * STAGE_FLOATS) * 4, &tmap,
                       x0 + (int)s_oxa[lf], y0 + (int)s_oymin[lf], pbase + lf,
                       mbar);
        } else {
            mbar_arrive(mbar);   // flip phase; compute takes global fallback
        }
    };

    // Prologue: issue lambdas 0..PFD-1 into stages 0..PFD-1 (fresh).
    if (tid == 0) {
#pragma unroll
        for (int l = 0; l < PFD && l < LCHUNK; ++l) issue(l, l % NSTAGE);
    }

    int stage = 0, parity = 0;            // stage/parity of lambda l
    int stage_p = PFD % NSTAGE;           // stage of lambda l+PFD
    for (int l = 0; l < LCHUNK; ++l) {
        __syncthreads();   // all threads finished compute(l-1) (=> l-2 free)
        // Issue fill(l+PFD): targets stage (l+PFD)%5 == (l-2)%5 — free above.
        if (tid == 0 && l + PFD < LCHUNK) issue(l + PFD, stage_p);
        // Wait for fill(l).
        mbar_wait(mb0 + 8 * stage, parity);

        const float* buf = s_dyn + stage * STAGE_FLOATS;
        const int oym = s_oymin[l];
        const int oxa = s_oxa[l];

        if (s_okf[l]) {
#pragma unroll
            for (int k = 0; k < NK; ++k) {
                const int2 off = s_off[l * 4 + k];
                const int obase = off.x - oxa + 2 * tx;
                const int rbase = 2 * ty + off.y - oym;
                const float* bp = buf + rbase * RSTRIDE + obase;
                ull p01[3], p12[3];
                if ((obase & 1) == 0) {
#pragma unroll
                    for (int r = 0; r < 3; ++r) {
                        const ull u = *reinterpret_cast<const ull*>(bp + r * RSTRIDE);
                        const float v2s = bp[r * RSTRIDE + 2];
                        float lo_, hi_; unpack2(u, lo_, hi_);
                        p01[r] = u;
                        p12[r] = pack2(hi_, v2s);
                    }
                } else {
#pragma unroll
                    for (int r = 0; r < 3; ++r) {
                        const float v0 = bp[r * RSTRIDE];
                        const ull u = *reinterpret_cast<const ull*>(bp + r * RSTRIDE + 1);
                        float lo_, hi_; unpack2(u, lo_, hi_);
                        p01[r] = pack2(v0, lo_);
                        p12[r] = u;
                    }
                }
                const WPack wp = s_wt[l * 4 + k];
                fma2(acc[k][0], wp.w00, p01[0]);
                fma2(acc[k][0], wp.w01, p12[0]);
                fma2(acc[k][0], wp.w10, p01[1]);
                fma2(acc[k][0], wp.w11, p12[1]);
                fma2(acc[k][1], wp.w00, p01[1]);
                fma2(acc[k][1], wp.w01, p12[1]);
                fma2(acc[k][1], wp.w10, p01[2]);
                fma2(acc[k][1], wp.w11, p12[2]);
            }
        } else {
            // Rare fallback: offsets too spread for the smem tile — global.
            const float* img = imgb + (size_t)l * (H * W);
#pragma unroll
            for (int k = 0; k < NK; ++k) {
                const int2 off = s_off[l * 4 + k];
                float w00, w01, w10, w11, d0;
                unpack2(s_wt[l * 4 + k].w00, w00, d0);
                unpack2(s_wt[l * 4 + k].w01, w01, d0);
                unpack2(s_wt[l * 4 + k].w10, w10, d0);
                unpack2(s_wt[l * 4 + k].w11, w11, d0);
#pragma unroll
                for (int r = 0; r < 2; ++r) {
                    float s[2];
#pragma unroll
                    for (int c = 0; c < 2; ++c) {
                        const int iy0 = y0 + 2 * ty + r + off.y;
                        const int ix0 = x0 + 2 * tx + c + off.x;
                        const bool y0ok = (unsigned)iy0       < (unsigned)H;
                        const bool y1ok = (unsigned)(iy0 + 1) < (unsigned)H;
                        const bool x0ok = (unsigned)ix0       < (unsigned)W;
                        const bool x1ok = (unsigned)(ix0 + 1) < (unsigned)W;
                        const float v00 = (y0ok && x0ok) ? __ldg(&img[iy0 * W + ix0])           : 0.f;
                        const float v01 = (y0ok && x1ok) ? __ldg(&img[iy0 * W + ix0 + 1])       : 0.f;
                        const float v10 = (y1ok && x0ok) ? __ldg(&img[(iy0 + 1) * W + ix0])     : 0.f;
                        const float v11 = (y1ok && x1ok) ? __ldg(&img[(iy0 + 1) * W + ix0 + 1]) : 0.f;
                        s[c] = w00 * v00 + w01 * v01 + w10 * v10 + w11 * v11;
                    }
                    fma2(acc[k][r], one2, pack2(s[0], s[1]));
                }
            }
        }

        if (++stage == NSTAGE)   { stage = 0; parity ^= 1; }
        if (++stage_p == NSTAGE) { stage_p = 0; }
    }

    // --- Write partials (float2 stores, 2 rows x 2 cols per k) ---
    float* gp = g_part + (size_t)chunk * (NB * NK * HO * WO)
                       + (size_t)b * (NK * HO * WO);
#pragma unroll
    for (int k = 0; k < NK; ++k) {
#pragma unroll
        for (int r = 0; r < 2; ++r) {
            float lo, hi;
            unpack2(acc[k][r], lo, hi);
            *reinterpret_cast<float2*>(
                &gp[(size_t)k * (HO * WO) + (y0 + 2 * ty + r) * WO + x0 + 2 * tx]) =
                make_float2(lo, hi);
        }
    }
}

// ---------------------------------------------------------------------------
// Pass 2: 15x15 PSF conv, 64x32 tile, 4x2 outputs/thread, f32x2 FMA.
// (R13 champion — unchanged.)
// ---------------------------------------------------------------------------
#define P2TX 64
#define P2TY 32
#define P2RC 78      // region cols: 64 + 14
#define P2RR 46      // region rows: 32 + 14
#define P2S  80      // smem stride (float4-aligned)

__global__ void __launch_bounds__(256)
psf_conv_kernel(const float* __restrict__ psf, float* __restrict__ out)
{
    __shared__ float s_acc[P2RR * P2S];        // 14.7 KB
    __shared__ ull   s_psf2[KS * KS];          // 1.8 KB

    const int tid = threadIdx.x;
    const int p   = blockIdx.z;                // plane: b*4+k
    const int x0  = blockIdx.x * P2TX;
    const int y0  = blockIdx.y * P2TY;

    if (tid < KS * KS) {
        const float w = __ldg(&psf[tid]);
        s_psf2[tid] = pack2(w, w);
    }

    const float* p0 = g_part + (size_t)p * (HO * WO);
    const size_t  pstep = (size_t)(NB * NK) * (HO * WO);

    // Load region: cols 0..63
    {
        const int c  = tid & 63;
        const int gx = x0 + c - KR;
        const bool xok = (unsigned)gx < (unsigned)WO;
#pragma unroll 4
        for (int r = tid >> 6; r < P2RR; r += 4) {
            const int gy = y0 + r - KR;
            float v = 0.f;
            if (xok && (unsigned)gy < (unsigned)HO) {
                const int idx = gy * WO + gx;
                v = __ldg(&p0[idx]) + __ldg(&p0[idx + pstep])
                  + __ldg(&p0[idx + 2 * pstep]) + __ldg(&p0[idx + 3 * pstep]);
            }
            s_acc[r * P2S + c] = v;
        }
    }
    // Load region: cols 64..77
    {
        const int c  = 64 + (tid & 15);
        const int gx = x0 + c - KR;
        const bool cok = c < P2RC;
        const bool xok = cok && (unsigned)gx < (unsigned)WO;
#pragma unroll
        for (int r = tid >> 4; r < P2RR; r += 16) {
            const int gy = y0 + r - KR;
            float v = 0.f;
            if (xok && (unsigned)gy < (unsigned)HO) {
                const int idx = gy * WO + gx;
                v = __ldg(&p0[idx]) + __ldg(&p0[idx + pstep])
                  + __ldg(&p0[idx + 2 * pstep]) + __ldg(&p0[idx + 3 * pstep]);
            }
            if (cok) s_acc[r * P2S + c] = v;
        }
    }
    __syncthreads();

    const int tx = (tid & 15) * 4;   // 0..60
    const int ty = (tid >> 4) * 2;   // 0..30

    ull acc00 = 0, acc01 = 0, acc10 = 0, acc11 = 0;
    ull pp[17];

    auto load_pack = [&](int v) {
        float row[20];
        const float4* rp = reinterpret_cast<const float4*>(&s_acc[(ty + v) * P2S + tx]);
#pragma unroll
        for (int q = 0; q < 5; ++q) {
            const float4 t = rp[q];
            row[4*q+0] = t.x; row[4*q+1] = t.y; row[4*q+2] = t.z; row[4*q+3] = t.w;
        }
#pragma unroll
        for (int j = 0; j < 17; ++j) pp[j] = pack2(row[j], row[j+1]);
    };

    // v = 0: contributes only to output row 0 (ky = 0)
    load_pack(0);
#pragma unroll
    for (int kx = 0; kx < KS; ++kx) {
        const ull w = s_psf2[kx];
        fma2(acc00, w, pp[kx]);
        fma2(acc01, w, pp[kx + 2]);
    }
    // v = 1..14: contributes to both output rows
#pragma unroll 2
    for (int v = 1; v < KS; ++v) {
        load_pack(v);
#pragma unroll
        for (int kx = 0; kx < KS; ++kx) {
            const ull w0 = s_psf2[v * KS + kx];         // row 0, ky = v
            fma2(acc00, w0, pp[kx]);
            fma2(acc01, w0, pp[kx + 2]);
            const ull w1 = s_psf2[(v - 1) * KS + kx];   // row 1, ky = v-1
            fma2(acc10, w1, pp[kx]);
            fma2(acc11, w1, pp[kx + 2]);
        }
    }
    // v = 15: contributes only to output row 1 (ky = 14)
    load_pack(KS);
#pragma unroll
    for (int kx = 0; kx < KS; ++kx) {
        const ull w = s_psf2[(KS - 1) * KS + kx];
        fma2(acc10, w, pp[kx]);
        fma2(acc11, w, pp[kx + 2]);
    }

    float* op = out + (size_t)p * (HO * WO);
    const int ybase = y0 + ty;
    const int xbase = x0 + tx;
    float lo, hi;
    if (xbase < WO) {
        unpack2(acc00, lo, hi);
        *reinterpret_cast<float2*>(&op[ybase * WO + xbase]) = make_float2(lo, hi);
        unpack2(acc10, lo, hi);
        *reinterpret_cast<float2*>(&op[(ybase + 1) * WO + xbase]) = make_float2(lo, hi);
    }
    if (xbase + 2 < WO) {
        unpack2(acc01, lo, hi);
        *reinterpret_cast<float2*>(&op[ybase * WO + xbase + 2]) = make_float2(lo, hi);
        unpack2(acc11, lo, hi);
        *reinterpret_cast<float2*>(&op[(ybase + 1) * WO + xbase + 2]) = make_float2(lo, hi);
    }
}

// ---------------------------------------------------------------------------
// Host: build the cube tensor map (driver entry point via cudart — no -lcuda).
// ---------------------------------------------------------------------------
typedef CUresult (*PFN_tmapEncode)(
    CUtensorMap*, CUtensorMapDataType, cuuint32_t, void*,
    const cuuint64_t*, const cuuint64_t*, const cuuint32_t*, const cuuint32_t*,
    CUtensorMapInterleave, CUtensorMapSwizzle, CUtensorMapL2promotion,
    CUtensorMapFloatOOBfill);

extern "C" void kernel_launch(void* const* d_in, const int* in_sizes, int n_in,
                              void* d_out, int out_size)
{
    const float* cube = (const float*)d_in[0];   // (4, 96, 256, 256)
    const float* dx   = (const float*)d_in[1];   // (4, 96)
    const float* dy   = (const float*)d_in[2];   // (4, 96)
    const float* psf  = (const float*)d_in[3];   // (15, 15)
    float* out        = (float*)d_out;           // (4, 4, 288, 288)

    // Fetch cuTensorMapEncodeTiled through cudart (works without -lcuda).
    void* fp = nullptr;
#if CUDART_VERSION >= 12050
    cudaDriverEntryPointQueryResult qres;
    cudaGetDriverEntryPointByVersion("cuTensorMapEncodeTiled", &fp, 12000,
                                     cudaEnableDefault, &qres);
#else
    cudaGetDriverEntryPoint("cuTensorMapEncodeTiled", &fp, cudaEnableDefault);
#endif
    PFN_tmapEncode encode = (PFN_tmapEncode)fp;

    CUtensorMap tmap{};
    {
        cuuint64_t dims[3]    = {(cuuint64_t)W, (cuuint64_t)H,
                                 (cuuint64_t)(NB * NLAM)};
        cuuint64_t strides[2] = {(cuuint64_t)W * 4,
                                 (cuuint64_t)W * H * 4};
        cuuint32_t box[3]     = {REGCOLS, REGROWS, 1};
        cuuint32_t estr[3]    = {1, 1, 1};
        encode(&tmap, CU_TENSOR_MAP_DATA_TYPE_FLOAT32, 3, (void*)cube,
               dims, strides, box, estr,
               CU_TENSOR_MAP_INTERLEAVE_NONE, CU_TENSOR_MAP_SWIZZLE_NONE,
               CU_TENSOR_MAP_L2_PROMOTION_L2_128B,
               CU_TENSOR_MAP_FLOAT_OOB_FILL_NONE);
    }

    cudaFuncSetAttribute(shift_acc_kernel,
                         cudaFuncAttributeMaxDynamicSharedMemorySize, SMEM_DYN);

    dim3 g1(WO / TILE, HO / TILE, NB * NCHUNK);           // 9 x 9 x 16
    shift_acc_kernel<<<g1, 256, SMEM_DYN>>>(tmap, cube, dx, dy);

    dim3 g2((WO + P2TX - 1) / P2TX, HO / P2TY, NB * NK);  // 5 x 9 x 16
    psf_conv_kernel<<<g2, 256>>>(psf, out);
}